// round 10
// baseline (speedup 1.0000x reference)
#include <cuda_runtime.h>
#include <cuda_bf16.h>
#include <cstdint>
#include <math.h>

// ---------------- problem constants ----------------
constexpr int Bdim = 4;
constexpr int Tdim = 96;
constexpr int Ndim = 512;
constexpr int Hdim = 128;
constexpr int Mrows = Bdim * Tdim * Ndim;   // 196608
constexpr int NT64  = Mrows / 64;           // 3072 tiles for gemm2
constexpr int GRID2 = 296;                  // 2 CTAs per SM

// scratch (allocation-free rule)
__device__ __nv_bfloat16 g_gHi[(size_t)Mrows * Hdim];      // gated hi plane
__device__ __nv_bfloat16 g_gLo[(size_t)Mrows * Hdim];      // gated lo plane

// ---------------- helpers ----------------
__device__ __forceinline__ uint32_t smem_u32(const void* p) {
    uint32_t a;
    asm("{ .reg .u64 t; cvta.to.shared.u64 t, %1; cvt.u32.u64 %0, t; }"
        : "=r"(a) : "l"(p));
    return a;
}

#define LDSM4(r, addr)                                                        \
    asm volatile("ldmatrix.sync.aligned.m8n8.x4.shared.b16 {%0,%1,%2,%3}, [%4];" \
                 : "=r"((r)[0]), "=r"((r)[1]), "=r"((r)[2]), "=r"((r)[3])     \
                 : "r"(addr))

#define MMA16816(d, a, b0, b1)                                                \
    asm volatile("mma.sync.aligned.m16n8k16.row.col.f32.bf16.bf16.f32 "       \
                 "{%0,%1,%2,%3}, {%4,%5,%6,%7}, {%8,%9}, {%0,%1,%2,%3};"      \
                 : "+f"((d)[0]), "+f"((d)[1]), "+f"((d)[2]), "+f"((d)[3])     \
                 : "r"((a)[0]), "r"((a)[1]), "r"((a)[2]), "r"((a)[3]),        \
                   "r"(b0), "r"(b1))

#define WG_BAR(id)                                                            \
    asm volatile("bar.sync %0, %1;" :: "r"(id), "r"(128) : "memory")

constexpr int LDS_STRIDE = 136;  // 128 + 8 bf16 pad -> conflict-free smem

// fp32 x4 -> hi/lo bf16 pairs
__device__ __forceinline__ void split4(float4 v, uint2& hp, uint2& lp) {
    __nv_bfloat162 h0 = __float22bfloat162_rn(make_float2(v.x, v.y));
    __nv_bfloat162 h1 = __float22bfloat162_rn(make_float2(v.z, v.w));
    float2 h0f = __bfloat1622float2(h0);
    float2 h1f = __bfloat1622float2(h1);
    __nv_bfloat162 l0 = __float22bfloat162_rn(make_float2(v.x - h0f.x, v.y - h0f.y));
    __nv_bfloat162 l1 = __float22bfloat162_rn(make_float2(v.z - h1f.x, v.w - h1f.y));
    hp.x = *reinterpret_cast<uint32_t*>(&h0);
    hp.y = *reinterpret_cast<uint32_t*>(&h1);
    lp.x = *reinterpret_cast<uint32_t*>(&l0);
    lp.y = *reinterpret_cast<uint32_t*>(&l1);
}

// ---------------- fused GEMM1 + EMA + gate: warpgroup t-parity pipeline ----------------
// Grid 128 = (b 0..3) x (16-row n-chunk, 32). Block 256 = 2 warpgroups of 4 warps.
// wg0 handles even t, wg1 odd t. Each wg: stage own 16x128 A tile, full 16x256 GEMM,
// then the EMA scan via shared sS[16x128] guarded by a turn counter.
// Warp w of a wg owns primary cols [32w,+32) and gating cols [128+32w,+32).
constexpr int FS_W   = 0;                                   // sWhi/sWlo: 256 rows each
constexpr int FS_A   = 2 * 256 * LDS_STRIDE * 2;            // 139264: per-wg A hi/lo (16 rows)
constexpr int FS_G   = FS_A + 2 * (2 * 16 * LDS_STRIDE * 2);// 156672: per-wg G hi/lo
constexpr int FS_S   = FS_G + 2 * (2 * 16 * LDS_STRIDE * 2);// 174080: sS 16x128 fp32
constexpr int FS_T   = FS_S + 16 * 128 * 4;                 // 182272: turn counter
constexpr int FS_TOT = FS_T + 16;                           // 182288

__global__ __launch_bounds__(256, 1)
void mamba_fused(const float* __restrict__ x, const float* __restrict__ W_exp,
                 const float* __restrict__ bias) {
    extern __shared__ char smem[];
    __nv_bfloat16* sWhi = reinterpret_cast<__nv_bfloat16*>(smem);
    __nv_bfloat16* sWlo = sWhi + 256 * LDS_STRIDE;

    const int tid  = threadIdx.x;
    const int lane = tid & 31;
    const int wgid = tid >> 7;          // warpgroup 0/1
    const int w    = (tid >> 5) & 3;    // warp within wg
    const int wtid = tid & 127;
    const int b    = blockIdx.x >> 5;
    const int n0   = (blockIdx.x & 31) * 16;

    __nv_bfloat16* sAhi = reinterpret_cast<__nv_bfloat16*>(smem + FS_A) +
                          wgid * (2 * 16 * LDS_STRIDE);
    __nv_bfloat16* sAlo = sAhi + 16 * LDS_STRIDE;
    __nv_bfloat16* sGhi = reinterpret_cast<__nv_bfloat16*>(smem + FS_G) +
                          wgid * (2 * 16 * LDS_STRIDE);
    __nv_bfloat16* sGlo = sGhi + 16 * LDS_STRIDE;
    float* sS = reinterpret_cast<float*>(smem + FS_S);
    volatile int* vturn = reinterpret_cast<volatile int*>(smem + FS_T);

    // cooperative W convert (256 rows x 128): 8192 float4 over 256 threads
#pragma unroll 4
    for (int it = 0; it < 32; ++it) {
        int i = tid + it * 256;
        int r = i >> 5, c4 = (i & 31) << 2;
        float4 v = *reinterpret_cast<const float4*>(W_exp + (size_t)r * 128 + c4);
        uint2 hp, lp;
        split4(v, hp, lp);
        int off = r * LDS_STRIDE + c4;
        *reinterpret_cast<uint2*>(sWhi + off) = hp;
        *reinterpret_cast<uint2*>(sWlo + off) = lp;
    }
    // zero scan state + turn
    for (int i = tid; i < 16 * 128; i += 256) sS[i] = 0.0f;
    if (tid == 0) *vturn = 0;
    __syncthreads();

    // ldmatrix addresses
    uint32_t aHiAd, aLoAd, bHiAd[2][2], bLoAd[2][2];
    {
        const uint32_t aBH = smem_u32(sAhi), aBL = smem_u32(sAlo);
        const uint32_t bBH = smem_u32(sWhi), bBL = smem_u32(sWlo);
        uint32_t aoff = ((lane & 15) * LDS_STRIDE + (lane >> 4) * 8) * 2;
        aHiAd = aBH + aoff;
        aLoAd = aBL + aoff;
        int bc = ((lane >> 3) & 1) * 8;
#pragma unroll
        for (int p = 0; p < 2; ++p)
#pragma unroll
            for (int j = 0; j < 2; ++j) {
                int br = p * 128 + 32 * w + 16 * j + ((lane >> 4) << 3) + (lane & 7);
                uint32_t off = (br * LDS_STRIDE + bc) * 2;
                bHiAd[p][j] = bBH + off;
                bLoAd[p][j] = bBL + off;
            }
    }

    const int gr = lane >> 2;
    const int gc = (lane & 3) * 2;
    float bp[4][2], bg[4][2];
#pragma unroll
    for (int jj = 0; jj < 4; ++jj) {
        bp[jj][0] = bias[32 * w + jj * 8 + gc];
        bp[jj][1] = bias[32 * w + jj * 8 + gc + 1];
        bg[jj][0] = bias[128 + 32 * w + jj * 8 + gc];
        bg[jj][1] = bias[128 + 32 * w + jj * 8 + gc + 1];
    }

    // prefetch first tile (t = wgid): 16x128 fp32 = 512 float4 over 128 threads
    float4 pf[4];
    {
        size_t rb = ((size_t)(b * Tdim + wgid) * Ndim + n0) * 128;
#pragma unroll
        for (int it = 0; it < 4; ++it) {
            int i = wtid + it * 128;
            int r = i >> 5, c4 = (i & 31) << 2;
            pf[it] = *reinterpret_cast<const float4*>(x + rb + (size_t)r * 128 + c4);
        }
    }

    const int barid = wgid + 1;
    for (int t = wgid; t < Tdim; t += 2) {
        // stage A tile: fp32 -> split bf16 planes
#pragma unroll
        for (int it = 0; it < 4; ++it) {
            int i = wtid + it * 128;
            int r = i >> 5, c4 = (i & 31) << 2;
            uint2 hp, lp;
            split4(pf[it], hp, lp);
            int off = r * LDS_STRIDE + c4;
            *reinterpret_cast<uint2*>(sAhi + off) = hp;
            *reinterpret_cast<uint2*>(sAlo + off) = lp;
        }
        WG_BAR(barid);

        // prefetch t+2 (hidden under MMAs)
        if (t + 2 < Tdim) {
            size_t rb = ((size_t)(b * Tdim + t + 2) * Ndim + n0) * 128;
#pragma unroll
            for (int it = 0; it < 4; ++it) {
                int i = wtid + it * 128;
                int r = i >> 5, c4 = (i & 31) << 2;
                pf[it] = *reinterpret_cast<const float4*>(x + rb + (size_t)r * 128 + c4);
            }
        }

        float acc[2][4][4];   // [p: 0=primary 1=gating][jj][q]
#pragma unroll
        for (int p = 0; p < 2; ++p)
#pragma unroll
            for (int jj = 0; jj < 4; ++jj)
#pragma unroll
                for (int q = 0; q < 4; ++q) acc[p][jj][q] = 0.0f;

#pragma unroll
        for (int kk = 0; kk < 8; ++kk) {
            const uint32_t ko = kk * 32;
            uint32_t ah[4], al[4], bh[2][2][4], bl[2][2][4];
            LDSM4(ah, aHiAd + ko);
            LDSM4(al, aLoAd + ko);
#pragma unroll
            for (int p = 0; p < 2; ++p)
#pragma unroll
                for (int j = 0; j < 2; ++j) {
                    LDSM4(bh[p][j], bHiAd[p][j] + ko);
                    LDSM4(bl[p][j], bLoAd[p][j] + ko);
                }
#pragma unroll
            for (int p = 0; p < 2; ++p)
#pragma unroll
                for (int jj = 0; jj < 4; ++jj) {
                    const int j = jj >> 1, wh = (jj & 1) * 2;
                    float* d = acc[p][jj];
                    MMA16816(d, ah, bh[p][j][wh], bh[p][j][wh + 1]);
                    MMA16816(d, ah, bl[p][j][wh], bl[p][j][wh + 1]);
                    MMA16816(d, al, bh[p][j][wh], bh[p][j][wh + 1]);
                }
        }

        // wait our turn for the scan state
        while (*vturn < t) { __nanosleep(20); }
        __threadfence_block();

        // EMA scan + sigmoid gate; update shared state; stage split-bf16 to sG
#pragma unroll
        for (int jj = 0; jj < 4; ++jj) {
            float gt[4];
#pragma unroll
            for (int q = 0; q < 4; ++q) {
                int r = gr + (q >> 1) * 8;
                int c = 32 * w + jj * 8 + gc + (q & 1);
                int idx = r * 128 + c;
                float gv = acc[1][jj][q] + bg[jj][q & 1];
                float sv = fmaf(0.9f, sS[idx], 0.1f * gv);
                sS[idx] = sv;
                float sig = 1.0f / (1.0f + __expf(-sv));
                gt[q] = (acc[0][jj][q] + bp[jj][q & 1]) * sig;
            }
            const int col = 32 * w + jj * 8 + gc;
#pragma unroll
            for (int h2 = 0; h2 < 2; ++h2) {
                float2 pr2 = make_float2(gt[h2 * 2], gt[h2 * 2 + 1]);
                __nv_bfloat162 hi2 = __float22bfloat162_rn(pr2);
                float2 hif = __bfloat1622float2(hi2);
                __nv_bfloat162 lo2 = __float22bfloat162_rn(
                    make_float2(pr2.x - hif.x, pr2.y - hif.y));
                int row = gr + h2 * 8;
                *reinterpret_cast<uint32_t*>(sGhi + row * LDS_STRIDE + col) =
                    *reinterpret_cast<uint32_t*>(&hi2);
                *reinterpret_cast<uint32_t*>(sGlo + row * LDS_STRIDE + col) =
                    *reinterpret_cast<uint32_t*>(&lo2);
            }
        }
        WG_BAR(barid);                    // drains sS + sG stores of this wg
        if (wtid == 0) {
            __threadfence_block();
            *vturn = t + 1;               // release the turn to the other wg
        }

        // coalesced store: 16 rows x 128 bf16 per plane (2 uint4/thread/plane)
#pragma unroll
        for (int it = 0; it < 2; ++it) {
            int i = wtid + it * 128;
            int r = i >> 4, c8 = (i & 15) << 3;
            uint4 vh = *reinterpret_cast<const uint4*>(sGhi + r * LDS_STRIDE + c8);
            uint4 vl = *reinterpret_cast<const uint4*>(sGlo + r * LDS_STRIDE + c8);
            size_t g = ((size_t)(b * Tdim + t) * Ndim + n0 + r) * 128 + c8;
            *reinterpret_cast<uint4*>(g_gHi + g) = vh;
            *reinterpret_cast<uint4*>(g_gLo + g) = vl;
        }
    }
}

// ---------------- GEMM2: persistent 64-row tiles, 2 CTAs/SM ----------------
__global__ __launch_bounds__(256, 2)
void gemm2_p(const float* __restrict__ W_con, const float* __restrict__ bias,
             float* __restrict__ C) {
    extern __shared__ char smem[];
    __nv_bfloat16* sWhi = reinterpret_cast<__nv_bfloat16*>(smem);   // 128 rows
    __nv_bfloat16* sWlo = sWhi + 128 * LDS_STRIDE;
    __nv_bfloat16* sAhi = sWlo + 128 * LDS_STRIDE;                  // 64 rows
    __nv_bfloat16* sAlo = sAhi + 64 * LDS_STRIDE;

    const int tid  = threadIdx.x;
    const int wid  = tid >> 5;
    const int lane = tid & 31;

    // W convert: 4096 float4 over 256 threads
#pragma unroll 4
    for (int it = 0; it < 16; ++it) {
        int i = tid + it * 256;
        int r = i >> 5, c4 = (i & 31) << 2;
        float4 v = *reinterpret_cast<const float4*>(W_con + (size_t)r * 128 + c4);
        uint2 hp, lp;
        split4(v, hp, lp);
        int off = r * LDS_STRIDE + c4;
        *reinterpret_cast<uint2*>(sWhi + off) = hp;
        *reinterpret_cast<uint2*>(sWlo + off) = lp;
    }

    // warp layout: 2m x 4n, each 32x32 of the 64x128 tile
    const int m0 = (wid & 1) * 32;
    const int n0 = (wid >> 1) * 32;

    uint32_t aHiAd[2], aLoAd[2], bHiAd[2], bLoAd[2];
    {
        const uint32_t aBH = smem_u32(sAhi), aBL = smem_u32(sAlo);
        const uint32_t bBH = smem_u32(sWhi), bBL = smem_u32(sWlo);
        int ar = m0 + (lane & 15);
        int ac = (lane >> 4) * 8;
#pragma unroll
        for (int i = 0; i < 2; ++i) {
            uint32_t off = ((ar + 16 * i) * LDS_STRIDE + ac) * 2;
            aHiAd[i] = aBH + off;
            aLoAd[i] = aBL + off;
        }
        int br = n0 + ((lane >> 4) << 3) + (lane & 7);
        int bc = ((lane >> 3) & 1) * 8;
#pragma unroll
        for (int j = 0; j < 2; ++j) {
            uint32_t off = ((br + 16 * j) * LDS_STRIDE + bc) * 2;
            bHiAd[j] = bBH + off;
            bLoAd[j] = bBL + off;
        }
    }

    // prefetch tile0: 64x128 bf16 per plane = 1024 uint4, 4/thread/plane
    uint4 pfh[4], pfl[4];
    {
        int t0 = blockIdx.x;
        if (t0 < NT64) {
            const uint4* sh = reinterpret_cast<const uint4*>(g_gHi + (size_t)t0 * 64 * 128);
            const uint4* sl = reinterpret_cast<const uint4*>(g_gLo + (size_t)t0 * 64 * 128);
#pragma unroll
            for (int it = 0; it < 4; ++it) {
                pfh[it] = sh[tid + it * 256];
                pfl[it] = sl[tid + it * 256];
            }
        }
    }

    const int gr = lane >> 2;
    const int gc = (lane & 3) * 2;
    float bv[4][2];
#pragma unroll
    for (int jj = 0; jj < 4; ++jj) {
        bv[jj][0] = bias[n0 + jj * 8 + gc];
        bv[jj][1] = bias[n0 + jj * 8 + gc + 1];
    }

    for (int tile = blockIdx.x; tile < NT64; tile += GRID2) {
        __syncthreads();
#pragma unroll
        for (int it = 0; it < 4; ++it) {
            int i = tid + it * 256;
            int r = i >> 4, c = (i & 15) << 3;
            *reinterpret_cast<uint4*>(sAhi + r * LDS_STRIDE + c) = pfh[it];
            *reinterpret_cast<uint4*>(sAlo + r * LDS_STRIDE + c) = pfl[it];
        }
        __syncthreads();

        int next = tile + GRID2;
        if (next < NT64) {
            const uint4* sh = reinterpret_cast<const uint4*>(g_gHi + (size_t)next * 64 * 128);
            const uint4* sl = reinterpret_cast<const uint4*>(g_gLo + (size_t)next * 64 * 128);
#pragma unroll
            for (int it = 0; it < 4; ++it) {
                pfh[it] = sh[tid + it * 256];
                pfl[it] = sl[tid + it * 256];
            }
        }

        float acc[2][4][4];
#pragma unroll
        for (int i = 0; i < 2; ++i)
#pragma unroll
            for (int j = 0; j < 4; ++j)
#pragma unroll
                for (int q = 0; q < 4; ++q) acc[i][j][q] = 0.0f;

#pragma unroll
        for (int kk = 0; kk < 8; ++kk) {
            const uint32_t ko = kk * 32;
            uint32_t ah[2][4], al[2][4], bh[2][4], bl[2][4];
#pragma unroll
            for (int i = 0; i < 2; ++i) { LDSM4(ah[i], aHiAd[i] + ko); }
#pragma unroll
            for (int j = 0; j < 2; ++j) { LDSM4(bh[j], bHiAd[j] + ko); }
#pragma unroll
            for (int i = 0; i < 2; ++i) { LDSM4(al[i], aLoAd[i] + ko); }
#pragma unroll
            for (int j = 0; j < 2; ++j) { LDSM4(bl[j], bLoAd[j] + ko); }
#pragma unroll
            for (int i = 0; i < 2; ++i) {
#pragma unroll
                for (int jj = 0; jj < 4; ++jj) {
                    const int pr = jj >> 1, wh = (jj & 1) * 2;
                    float* d = acc[i][jj];
                    MMA16816(d, ah[i], bh[pr][wh], bh[pr][wh + 1]);
                    MMA16816(d, ah[i], bl[pr][wh], bl[pr][wh + 1]);
                    MMA16816(d, al[i], bh[pr][wh], bh[pr][wh + 1]);
                }
            }
        }

        const int bm0 = tile * 64;
#pragma unroll
        for (int jj = 0; jj < 4; ++jj) {
            const int col = n0 + jj * 8 + gc;
#pragma unroll
            for (int i = 0; i < 2; ++i) {
                const int row = bm0 + m0 + i * 16 + gr;
                float2 o0, o1;
                o0.x = acc[i][jj][0] + bv[jj][0]; o0.y = acc[i][jj][1] + bv[jj][1];
                o1.x = acc[i][jj][2] + bv[jj][0]; o1.y = acc[i][jj][3] + bv[jj][1];
                *reinterpret_cast<float2*>(&C[(size_t)row * 128 + col])       = o0;
                *reinterpret_cast<float2*>(&C[(size_t)(row + 8) * 128 + col]) = o1;
            }
        }
    }
}

// ---------------- launch ----------------
extern "C" void kernel_launch(void* const* d_in, const int* in_sizes, int n_in,
                              void* d_out, int out_size) {
    const float* x     = (const float*)d_in[0];
    const float* W_exp = (const float*)d_in[1];
    const float* b_exp = (const float*)d_in[2];
    const float* W_con = (const float*)d_in[3];
    const float* b_con = (const float*)d_in[4];
    float* out = (float*)d_out;

    constexpr int SMEMF = FS_TOT;                               // 182288
    constexpr int SMEM2 = (2 * 128 + 2 * 64) * LDS_STRIDE * 2;  // 104448
    cudaFuncSetAttribute(mamba_fused, cudaFuncAttributeMaxDynamicSharedMemorySize, SMEMF);
    cudaFuncSetAttribute(gemm2_p, cudaFuncAttributeMaxDynamicSharedMemorySize, SMEM2);

    mamba_fused<<<Bdim * 32, 256, SMEMF>>>(x, W_exp, b_exp);

    gemm2_p<<<GRID2, 256, SMEM2>>>(W_con, b_con, out);
}

// round 11
// speedup vs baseline: 1.0365x; 1.0365x over previous
#include <cuda_runtime.h>
#include <cuda_bf16.h>
#include <cstdint>
#include <math.h>

// ---------------- problem constants ----------------
constexpr int Bdim = 4;
constexpr int Tdim = 96;
constexpr int Ndim = 512;
constexpr int Hdim = 128;
constexpr int Mrows = Bdim * Tdim * Ndim;   // 196608
constexpr int NT2   = Mrows / 128;          // 1536 tiles for gemm2
constexpr int GRID_P = 148;

// scratch (allocation-free rule)
__device__ __nv_bfloat16 g_gHi[(size_t)Mrows * Hdim];      // gated hi plane
__device__ __nv_bfloat16 g_gLo[(size_t)Mrows * Hdim];      // gated lo plane

// ---------------- helpers ----------------
__device__ __forceinline__ uint32_t smem_u32(const void* p) {
    uint32_t a;
    asm("{ .reg .u64 t; cvta.to.shared.u64 t, %1; cvt.u32.u64 %0, t; }"
        : "=r"(a) : "l"(p));
    return a;
}

#define LDSM4(r, addr)                                                        \
    asm volatile("ldmatrix.sync.aligned.m8n8.x4.shared.b16 {%0,%1,%2,%3}, [%4];" \
                 : "=r"((r)[0]), "=r"((r)[1]), "=r"((r)[2]), "=r"((r)[3])     \
                 : "r"(addr))

#define MMA16816(d, a, b0, b1)                                                \
    asm volatile("mma.sync.aligned.m16n8k16.row.col.f32.bf16.bf16.f32 "       \
                 "{%0,%1,%2,%3}, {%4,%5,%6,%7}, {%8,%9}, {%0,%1,%2,%3};"      \
                 : "+f"((d)[0]), "+f"((d)[1]), "+f"((d)[2]), "+f"((d)[3])     \
                 : "r"((a)[0]), "r"((a)[1]), "r"((a)[2]), "r"((a)[3]),        \
                   "r"(b0), "r"(b1))

#define WG_BAR(id)                                                            \
    asm volatile("bar.sync %0, %1;" :: "r"(id), "r"(128) : "memory")

constexpr int LDS_STRIDE = 136;  // 128 + 8 bf16 pad -> conflict-free smem

// fp32 x4 -> hi/lo bf16 pairs
__device__ __forceinline__ void split4(float4 v, uint2& hp, uint2& lp) {
    __nv_bfloat162 h0 = __float22bfloat162_rn(make_float2(v.x, v.y));
    __nv_bfloat162 h1 = __float22bfloat162_rn(make_float2(v.z, v.w));
    float2 h0f = __bfloat1622float2(h0);
    float2 h1f = __bfloat1622float2(h1);
    __nv_bfloat162 l0 = __float22bfloat162_rn(make_float2(v.x - h0f.x, v.y - h0f.y));
    __nv_bfloat162 l1 = __float22bfloat162_rn(make_float2(v.z - h1f.x, v.w - h1f.y));
    hp.x = *reinterpret_cast<uint32_t*>(&h0);
    hp.y = *reinterpret_cast<uint32_t*>(&h1);
    lp.x = *reinterpret_cast<uint32_t*>(&l0);
    lp.y = *reinterpret_cast<uint32_t*>(&l1);
}

// ---------------- fused GEMM1 + EMA + gate: 2 independent streams per CTA ----------------
// Grid 128 CTAs x 256 thr. Stream = (64-feature slice, b, 16-row n-chunk).
// CTA i: slice = i>>6, b = (i>>4)&3, n-chunk pair = {2*(i&15), 2*(i&15)+1}.
// wg0 (thr 0-127) runs chunk 2k, wg1 runs chunk 2k+1 -- fully independent t-loops,
// sharing only the read-only W slice in smem (converted once per CTA).
// Warp w of a wg owns primary cols [f0+16w,+16) and gating cols [128+f0+16w,+16).
__global__ __launch_bounds__(256, 1)
void mamba_fused(const float* __restrict__ x, const float* __restrict__ W_exp,
                 const float* __restrict__ bias) {
    extern __shared__ char smem[];
    __nv_bfloat16* sWhi = reinterpret_cast<__nv_bfloat16*>(smem);   // 128 rows (slice)
    __nv_bfloat16* sWlo = sWhi + 128 * LDS_STRIDE;

    const int tid   = threadIdx.x;
    const int lane  = tid & 31;
    const int wgid  = tid >> 7;
    const int w     = (tid >> 5) & 3;
    const int wtid  = tid & 127;
    const int slice = blockIdx.x >> 6;
    const int b     = (blockIdx.x >> 4) & 3;
    const int n0    = ((blockIdx.x & 15) * 2 + wgid) * 16;
    const int f0    = slice * 64;

    __nv_bfloat16* wgBase = sWlo + 128 * LDS_STRIDE + wgid * (4 * 16 * LDS_STRIDE);
    __nv_bfloat16* sAhi = wgBase;
    __nv_bfloat16* sAlo = sAhi + 16 * LDS_STRIDE;
    __nv_bfloat16* sGhi = sAlo + 16 * LDS_STRIDE;
    __nv_bfloat16* sGlo = sGhi + 16 * LDS_STRIDE;

    // cooperative W-slice convert (128 rows: 64 primary + 64 gating), once per CTA
#pragma unroll 4
    for (int it = 0; it < 16; ++it) {
        int i = tid + it * 256;        // 4096 float4
        int r = i >> 5, c4 = (i & 31) << 2;
        int srow = (r < 64) ? (f0 + r) : (64 + f0 + r);   // gating rows: 128+f0+(r-64)
        float4 v = *reinterpret_cast<const float4*>(W_exp + (size_t)srow * 128 + c4);
        uint2 hp, lp;
        split4(v, hp, lp);
        int off = r * LDS_STRIDE + c4;
        *reinterpret_cast<uint2*>(sWhi + off) = hp;
        *reinterpret_cast<uint2*>(sWlo + off) = lp;
    }

    // ldmatrix addresses
    uint32_t aHiAd, aLoAd, bHiAd[2], bLoAd[2];
    {
        const uint32_t aBH = smem_u32(sAhi), aBL = smem_u32(sAlo);
        const uint32_t bBH = smem_u32(sWhi), bBL = smem_u32(sWlo);
        uint32_t aoff = ((lane & 15) * LDS_STRIDE + (lane >> 4) * 8) * 2;
        aHiAd = aBH + aoff;
        aLoAd = aBL + aoff;
        int bc = ((lane >> 3) & 1) * 8;
#pragma unroll
        for (int p = 0; p < 2; ++p) {
            int br = p * 64 + 16 * w + ((lane >> 4) << 3) + (lane & 7);
            uint32_t off = (br * LDS_STRIDE + bc) * 2;
            bHiAd[p] = bBH + off;
            bLoAd[p] = bBL + off;
        }
    }

    const int gr = lane >> 2;
    const int gc = (lane & 3) * 2;
    float bp[2][2], bg[2][2];
#pragma unroll
    for (int jj = 0; jj < 2; ++jj) {
        bp[jj][0] = bias[f0 + 16 * w + jj * 8 + gc];
        bp[jj][1] = bias[f0 + 16 * w + jj * 8 + gc + 1];
        bg[jj][0] = bias[128 + f0 + 16 * w + jj * 8 + gc];
        bg[jj][1] = bias[128 + f0 + 16 * w + jj * 8 + gc + 1];
    }

    // EMA state (per-lane share of this warp's 16x16 gating block)
    float s[2][4];
#pragma unroll
    for (int jj = 0; jj < 2; ++jj)
#pragma unroll
        for (int q = 0; q < 4; ++q) s[jj][q] = 0.0f;

    // prefetch t = 0: 16x128 fp32 = 512 float4 over 128 threads
    float4 pf[4];
    {
        size_t rb = ((size_t)(b * Tdim) * Ndim + n0) * 128;
#pragma unroll
        for (int it = 0; it < 4; ++it) {
            int i = wtid + it * 128;
            int r = i >> 5, c4 = (i & 31) << 2;
            pf[it] = *reinterpret_cast<const float4*>(x + rb + (size_t)r * 128 + c4);
        }
    }
    __syncthreads();   // W-slice ready; wgs are independent from here on

    const int barid = wgid + 1;
    for (int t = 0; t < Tdim; ++t) {
        // stage A tile: fp32 -> split bf16 planes
#pragma unroll
        for (int it = 0; it < 4; ++it) {
            int i = wtid + it * 128;
            int r = i >> 5, c4 = (i & 31) << 2;
            uint2 hp, lp;
            split4(pf[it], hp, lp);
            int off = r * LDS_STRIDE + c4;
            *reinterpret_cast<uint2*>(sAhi + off) = hp;
            *reinterpret_cast<uint2*>(sAlo + off) = lp;
        }
        WG_BAR(barid);

        // prefetch next t (hidden under MMAs)
        if (t + 1 < Tdim) {
            size_t rb = ((size_t)(b * Tdim + t + 1) * Ndim + n0) * 128;
#pragma unroll
            for (int it = 0; it < 4; ++it) {
                int i = wtid + it * 128;
                int r = i >> 5, c4 = (i & 31) << 2;
                pf[it] = *reinterpret_cast<const float4*>(x + rb + (size_t)r * 128 + c4);
            }
        }

        float acc[2][2][4];   // [p: 0=primary 1=gating][jj][q]
#pragma unroll
        for (int p = 0; p < 2; ++p)
#pragma unroll
            for (int jj = 0; jj < 2; ++jj)
#pragma unroll
                for (int q = 0; q < 4; ++q) acc[p][jj][q] = 0.0f;

#pragma unroll
        for (int kk = 0; kk < 8; ++kk) {
            const uint32_t ko = kk * 32;
            uint32_t ah[4], al[4], bh[2][4], bl[2][4];
            LDSM4(ah, aHiAd + ko);
            LDSM4(bh[0], bHiAd[0] + ko);
            LDSM4(bh[1], bHiAd[1] + ko);
            LDSM4(al, aLoAd + ko);
            LDSM4(bl[0], bLoAd[0] + ko);
            LDSM4(bl[1], bLoAd[1] + ko);
#pragma unroll
            for (int p = 0; p < 2; ++p) {
#pragma unroll
                for (int jj = 0; jj < 2; ++jj) {
                    const int wh = jj * 2;
                    float* d = acc[p][jj];
                    MMA16816(d, ah, bh[p][wh], bh[p][wh + 1]);
                    MMA16816(d, ah, bl[p][wh], bl[p][wh + 1]);
                    MMA16816(d, al, bh[p][wh], bh[p][wh + 1]);
                }
            }
        }

        // in-register scan + gate + split; stage this wg's 16x64 slice to smem
#pragma unroll
        for (int jj = 0; jj < 2; ++jj) {
            float gt[4];
#pragma unroll
            for (int q = 0; q < 4; ++q) {
                float gv = acc[1][jj][q] + bg[jj][q & 1];
                s[jj][q] = fmaf(0.9f, s[jj][q], 0.1f * gv);
                float sig = 1.0f / (1.0f + __expf(-s[jj][q]));
                gt[q] = (acc[0][jj][q] + bp[jj][q & 1]) * sig;
            }
            const int col = 16 * w + jj * 8 + gc;
#pragma unroll
            for (int h2 = 0; h2 < 2; ++h2) {
                float2 pr2 = make_float2(gt[h2 * 2], gt[h2 * 2 + 1]);
                __nv_bfloat162 hi2 = __float22bfloat162_rn(pr2);
                float2 hif = __bfloat1622float2(hi2);
                __nv_bfloat162 lo2 = __float22bfloat162_rn(
                    make_float2(pr2.x - hif.x, pr2.y - hif.y));
                int row = gr + h2 * 8;
                *reinterpret_cast<uint32_t*>(sGhi + row * LDS_STRIDE + col) =
                    *reinterpret_cast<uint32_t*>(&hi2);
                *reinterpret_cast<uint32_t*>(sGlo + row * LDS_STRIDE + col) =
                    *reinterpret_cast<uint32_t*>(&lo2);
            }
        }
        WG_BAR(barid);   // sG ready + all MMAs done (safe to restage sA next iter)

        // coalesced store: 16 rows x 64 bf16 per plane (1 uint4/thread/plane)
        {
            int r = wtid >> 3, c8 = (wtid & 7) << 3;
            uint4 vh = *reinterpret_cast<const uint4*>(sGhi + r * LDS_STRIDE + c8);
            uint4 vl = *reinterpret_cast<const uint4*>(sGlo + r * LDS_STRIDE + c8);
            size_t g = ((size_t)(b * Tdim + t) * Ndim + n0 + r) * 128 + f0 + c8;
            *reinterpret_cast<uint4*>(g_gHi + g) = vh;
            *reinterpret_cast<uint4*>(g_gLo + g) = vl;
        }
    }
}

// ---------------- GEMM2 (persistent, 128-row tiles): out = gated*W_con^T + b ----------------
__global__ __launch_bounds__(512, 1)
void gemm2_p(const float* __restrict__ W_con, const float* __restrict__ bias,
             float* __restrict__ C) {
    extern __shared__ char smem[];
    __nv_bfloat16* sWhi = reinterpret_cast<__nv_bfloat16*>(smem);   // 128 rows
    __nv_bfloat16* sWlo = sWhi + 128 * LDS_STRIDE;
    __nv_bfloat16* sAhi = sWlo + 128 * LDS_STRIDE;                  // 128 rows
    __nv_bfloat16* sAlo = sAhi + 128 * LDS_STRIDE;

    const int tid  = threadIdx.x;
    const int wid  = tid >> 5;
    const int lane = tid & 31;

    // convert W_con fp32 -> split bf16 smem (one-time)
#pragma unroll
    for (int it = 0; it < 8; ++it) {
        int i = tid + it * 512;        // 4096 float4
        int r = i >> 5;
        int c4 = (i & 31) << 2;
        float4 v = *reinterpret_cast<const float4*>(W_con + (size_t)r * 128 + c4);
        uint2 hp, lp;
        split4(v, hp, lp);
        int off = r * LDS_STRIDE + c4;
        *reinterpret_cast<uint2*>(sWhi + off) = hp;
        *reinterpret_cast<uint2*>(sWlo + off) = lp;
    }

    // warp layout: 4m x 4n, each 32x32 of 128x128 tile
    const int m0 = (wid & 3) * 32;
    const int n0 = (wid >> 2) * 32;

    uint32_t aHiAd[2], aLoAd[2], bHiAd[2], bLoAd[2];
    {
        const uint32_t aBH = smem_u32(sAhi), aBL = smem_u32(sAlo);
        const uint32_t bBH = smem_u32(sWhi), bBL = smem_u32(sWlo);
        int ar = m0 + (lane & 15);
        int ac = (lane >> 4) * 8;
#pragma unroll
        for (int i = 0; i < 2; ++i) {
            uint32_t off = ((ar + 16 * i) * LDS_STRIDE + ac) * 2;
            aHiAd[i] = aBH + off;
            aLoAd[i] = aBL + off;
        }
        int br = n0 + ((lane >> 4) << 3) + (lane & 7);
        int bc = ((lane >> 3) & 1) * 8;
#pragma unroll
        for (int j = 0; j < 2; ++j) {
            uint32_t off = ((br + 16 * j) * LDS_STRIDE + bc) * 2;
            bHiAd[j] = bBH + off;
            bLoAd[j] = bBL + off;
        }
    }

    // prefetch tile0: 128x128 bf16 per plane = 2048 uint4, 4/thread/plane
    uint4 pfh[4], pfl[4];
    {
        int t0 = blockIdx.x;
        if (t0 < NT2) {
            const uint4* sh = reinterpret_cast<const uint4*>(g_gHi + (size_t)t0 * 128 * 128);
            const uint4* sl = reinterpret_cast<const uint4*>(g_gLo + (size_t)t0 * 128 * 128);
#pragma unroll
            for (int it = 0; it < 4; ++it) {
                pfh[it] = sh[tid + it * 512];
                pfl[it] = sl[tid + it * 512];
            }
        }
    }

    const int gr = lane >> 2;
    const int gc = (lane & 3) * 2;
    float bv[4][2];
#pragma unroll
    for (int jj = 0; jj < 4; ++jj) {
        bv[jj][0] = bias[n0 + jj * 8 + gc];
        bv[jj][1] = bias[n0 + jj * 8 + gc + 1];
    }

    for (int tile = blockIdx.x; tile < NT2; tile += GRID_P) {
        __syncthreads();
#pragma unroll
        for (int it = 0; it < 4; ++it) {
            int i = tid + it * 512;
            int r = i >> 4, c = (i & 15) << 3;
            *reinterpret_cast<uint4*>(sAhi + r * LDS_STRIDE + c) = pfh[it];
            *reinterpret_cast<uint4*>(sAlo + r * LDS_STRIDE + c) = pfl[it];
        }
        __syncthreads();

        int next = tile + GRID_P;
        if (next < NT2) {
            const uint4* sh = reinterpret_cast<const uint4*>(g_gHi + (size_t)next * 128 * 128);
            const uint4* sl = reinterpret_cast<const uint4*>(g_gLo + (size_t)next * 128 * 128);
#pragma unroll
            for (int it = 0; it < 4; ++it) {
                pfh[it] = sh[tid + it * 512];
                pfl[it] = sl[tid + it * 512];
            }
        }

        float acc[2][4][4];
#pragma unroll
        for (int i = 0; i < 2; ++i)
#pragma unroll
            for (int j = 0; j < 4; ++j)
#pragma unroll
                for (int q = 0; q < 4; ++q) acc[i][j][q] = 0.0f;

#pragma unroll
        for (int kk = 0; kk < 8; ++kk) {
            const uint32_t ko = kk * 32;
            uint32_t ah[2][4], al[2][4], bh[2][4], bl[2][4];
#pragma unroll
            for (int i = 0; i < 2; ++i) { LDSM4(ah[i], aHiAd[i] + ko); }
#pragma unroll
            for (int j = 0; j < 2; ++j) { LDSM4(bh[j], bHiAd[j] + ko); }
#pragma unroll
            for (int i = 0; i < 2; ++i) { LDSM4(al[i], aLoAd[i] + ko); }
#pragma unroll
            for (int j = 0; j < 2; ++j) { LDSM4(bl[j], bLoAd[j] + ko); }
#pragma unroll
            for (int i = 0; i < 2; ++i) {
#pragma unroll
                for (int jj = 0; jj < 4; ++jj) {
                    const int pr = jj >> 1, wh = (jj & 1) * 2;
                    float* d = acc[i][jj];
                    MMA16816(d, ah[i], bh[pr][wh], bh[pr][wh + 1]);
                    MMA16816(d, ah[i], bl[pr][wh], bl[pr][wh + 1]);
                    MMA16816(d, al[i], bh[pr][wh], bh[pr][wh + 1]);
                }
            }
        }

        const int bm0 = tile * 128;
#pragma unroll
        for (int jj = 0; jj < 4; ++jj) {
            const int col = n0 + jj * 8 + gc;
#pragma unroll
            for (int i = 0; i < 2; ++i) {
                const int row = bm0 + m0 + i * 16 + gr;
                float2 o0, o1;
                o0.x = acc[i][jj][0] + bv[jj][0]; o0.y = acc[i][jj][1] + bv[jj][1];
                o1.x = acc[i][jj][2] + bv[jj][0]; o1.y = acc[i][jj][3] + bv[jj][1];
                *reinterpret_cast<float2*>(&C[(size_t)row * 128 + col])       = o0;
                *reinterpret_cast<float2*>(&C[(size_t)(row + 8) * 128 + col]) = o1;
            }
        }
    }
}

// ---------------- launch ----------------
extern "C" void kernel_launch(void* const* d_in, const int* in_sizes, int n_in,
                              void* d_out, int out_size) {
    const float* x     = (const float*)d_in[0];
    const float* W_exp = (const float*)d_in[1];
    const float* b_exp = (const float*)d_in[2];
    const float* W_con = (const float*)d_in[3];
    const float* b_con = (const float*)d_in[4];
    float* out = (float*)d_out;

    constexpr int SMEMF = (2 * 128 + 2 * 4 * 16) * LDS_STRIDE * 2;  // 104448
    constexpr int SMEM2 = 4 * 128 * LDS_STRIDE * 2;                 // 139264
    cudaFuncSetAttribute(mamba_fused, cudaFuncAttributeMaxDynamicSharedMemorySize, SMEMF);
    cudaFuncSetAttribute(gemm2_p, cudaFuncAttributeMaxDynamicSharedMemorySize, SMEM2);

    mamba_fused<<<128, 256, SMEMF>>>(x, W_exp, b_exp);

    gemm2_p<<<GRID_P, 512, SMEM2>>>(W_con, b_con, out);
}

// round 12
// speedup vs baseline: 1.1449x; 1.1046x over previous
#include <cuda_runtime.h>
#include <cuda_bf16.h>
#include <cstdint>
#include <math.h>

// ---------------- problem constants ----------------
constexpr int Bdim = 4;
constexpr int Tdim = 96;
constexpr int Ndim = 512;
constexpr int Hdim = 128;
constexpr int Mrows = Bdim * Tdim * Ndim;   // 196608
constexpr int NT2   = Mrows / 128;          // 1536 tiles for gemm2
constexpr int GRID_P = 148;

// scratch (allocation-free rule)
__device__ __nv_bfloat16 g_gHi[(size_t)Mrows * Hdim];      // gated hi plane
__device__ __nv_bfloat16 g_gLo[(size_t)Mrows * Hdim];      // gated lo plane
__device__ __nv_bfloat16 g_weHi[256 * 128];                // W_exp hi
__device__ __nv_bfloat16 g_weLo[256 * 128];                // W_exp lo

// ---------------- helpers ----------------
__device__ __forceinline__ uint32_t smem_u32(const void* p) {
    uint32_t a;
    asm("{ .reg .u64 t; cvta.to.shared.u64 t, %1; cvt.u32.u64 %0, t; }"
        : "=r"(a) : "l"(p));
    return a;
}

#define LDSM4(r, addr)                                                        \
    asm volatile("ldmatrix.sync.aligned.m8n8.x4.shared.b16 {%0,%1,%2,%3}, [%4];" \
                 : "=r"((r)[0]), "=r"((r)[1]), "=r"((r)[2]), "=r"((r)[3])     \
                 : "r"(addr))

#define MMA16816(d, a, b0, b1)                                                \
    asm volatile("mma.sync.aligned.m16n8k16.row.col.f32.bf16.bf16.f32 "       \
                 "{%0,%1,%2,%3}, {%4,%5,%6,%7}, {%8,%9}, {%0,%1,%2,%3};"      \
                 : "+f"((d)[0]), "+f"((d)[1]), "+f"((d)[2]), "+f"((d)[3])     \
                 : "r"((a)[0]), "r"((a)[1]), "r"((a)[2]), "r"((a)[3]),        \
                   "r"(b0), "r"(b1))

constexpr int LDS_STRIDE = 136;  // 128 + 8 bf16 pad -> conflict-free smem

// fp32 x4 -> hi/lo bf16 pairs
__device__ __forceinline__ void split4(float4 v, uint2& hp, uint2& lp) {
    __nv_bfloat162 h0 = __float22bfloat162_rn(make_float2(v.x, v.y));
    __nv_bfloat162 h1 = __float22bfloat162_rn(make_float2(v.z, v.w));
    float2 h0f = __bfloat1622float2(h0);
    float2 h1f = __bfloat1622float2(h1);
    __nv_bfloat162 l0 = __float22bfloat162_rn(make_float2(v.x - h0f.x, v.y - h0f.y));
    __nv_bfloat162 l1 = __float22bfloat162_rn(make_float2(v.z - h1f.x, v.w - h1f.y));
    hp.x = *reinterpret_cast<uint32_t*>(&h0);
    hp.y = *reinterpret_cast<uint32_t*>(&h1);
    lp.x = *reinterpret_cast<uint32_t*>(&l0);
    lp.y = *reinterpret_cast<uint32_t*>(&l1);
}

// bf16 plane [ROWS,128] row-major -> smem tile (stride 136), uint4 copies
template <int ROWS, int NTHREADS>
__device__ __forceinline__ void copy_plane(const __nv_bfloat16* __restrict__ src,
                                           __nv_bfloat16* __restrict__ dst, int tid) {
    const uint4* s = reinterpret_cast<const uint4*>(src);
#pragma unroll
    for (int it = 0; it < (ROWS * 16) / NTHREADS; ++it) {
        int i = tid + it * NTHREADS;
        int r = i >> 4;
        int c = (i & 15) << 3;
        *reinterpret_cast<uint4*>(dst + r * LDS_STRIDE + c) = s[i];
    }
}

// ---------------- W_exp pre-split ----------------
__global__ __launch_bounds__(256)
void split_weights(const float* __restrict__ We) {
    int i = blockIdx.x * blockDim.x + threadIdx.x;
    if (i < 256 * 128) {
        float w = We[i];
        __nv_bfloat16 h = __float2bfloat16_rn(w);
        g_weHi[i] = h;
        g_weLo[i] = __float2bfloat16_rn(w - __bfloat162float(h));
    }
}

// ---------------- fused GEMM1 + EMA scan + gate ----------------
// Grid: 128 CTAs = (b 0..3) x (16-row n-chunk, 32). Block: 256 (8 warps).
// CTA walks t = 0..95 sequentially; EMA state lives in registers.
// Warp w owns primary cols [16w,16w+16) (3-pass split-bf16 MMA) and gating
// cols [128+16w,+16) (1-pass bf16 MMA -- error damped by EMA x0.23 and
// sigmoid slope <=0.25 before touching the output path).
__global__ __launch_bounds__(256, 1)
void gemm1_fused(const float* __restrict__ x, const float* __restrict__ bias) {
    extern __shared__ char smem[];
    __nv_bfloat16* sWhi = reinterpret_cast<__nv_bfloat16*>(smem);   // 256 rows
    __nv_bfloat16* sWlo = sWhi + 256 * LDS_STRIDE;
    __nv_bfloat16* sAhi = sWlo + 256 * LDS_STRIDE;                  // 16 rows
    __nv_bfloat16* sAlo = sAhi + 16 * LDS_STRIDE;
    __nv_bfloat16* sGhi = sAlo + 16 * LDS_STRIDE;                   // 16 rows
    __nv_bfloat16* sGlo = sGhi + 16 * LDS_STRIDE;

    const int tid  = threadIdx.x;
    const int wid  = tid >> 5;
    const int lane = tid & 31;
    const int b    = blockIdx.x >> 5;
    const int n0   = (blockIdx.x & 31) * 16;

    copy_plane<256, 256>(g_weHi, sWhi, tid);
    copy_plane<256, 256>(g_weLo, sWlo, tid);

    // ldmatrix addresses
    uint32_t aHiAd, aLoAd, bHiAd[2], bLoAd;
    {
        const uint32_t aBH = smem_u32(sAhi), aBL = smem_u32(sAlo);
        const uint32_t bBH = smem_u32(sWhi), bBL = smem_u32(sWlo);
        uint32_t aoff = ((lane & 15) * LDS_STRIDE + (lane >> 4) * 8) * 2;
        aHiAd = aBH + aoff;
        aLoAd = aBL + aoff;
        int bc = ((lane >> 3) & 1) * 8;
#pragma unroll
        for (int p = 0; p < 2; ++p) {
            int br = p * 128 + 16 * wid + ((lane >> 4) << 3) + (lane & 7);
            uint32_t off = (br * LDS_STRIDE + bc) * 2;
            bHiAd[p] = bBH + off;
            if (p == 0) bLoAd = bBL + off;   // lo plane needed only for primary
        }
    }

    const int gr = lane >> 2;
    const int gc = (lane & 3) * 2;
    float bp[2][2], bg[2][2];
#pragma unroll
    for (int jj = 0; jj < 2; ++jj) {
        bp[jj][0] = bias[16 * wid + jj * 8 + gc];
        bp[jj][1] = bias[16 * wid + jj * 8 + gc + 1];
        bg[jj][0] = bias[128 + 16 * wid + jj * 8 + gc];
        bg[jj][1] = bias[128 + 16 * wid + jj * 8 + gc + 1];
    }

    // EMA state (per-lane share of this warp's 16x16 gating block)
    float s[2][4];
#pragma unroll
    for (int jj = 0; jj < 2; ++jj)
#pragma unroll
        for (int q = 0; q < 4; ++q) s[jj][q] = 0.0f;

    // prefetch t = 0: 16x128 fp32 = 512 float4, 2 per thread
    float4 pf[2];
    {
        size_t rb = ((size_t)(b * Tdim) * Ndim + n0) * 128;
#pragma unroll
        for (int it = 0; it < 2; ++it) {
            int i = tid + it * 256;
            int r = i >> 5, c4 = (i & 31) << 2;
            pf[it] = *reinterpret_cast<const float4*>(x + rb + (size_t)r * 128 + c4);
        }
    }

    for (int t = 0; t < Tdim; ++t) {
        // stage A tile: fp32 -> split bf16 planes
#pragma unroll
        for (int it = 0; it < 2; ++it) {
            int i = tid + it * 256;
            int r = i >> 5, c4 = (i & 31) << 2;
            uint2 hp, lp;
            split4(pf[it], hp, lp);
            int off = r * LDS_STRIDE + c4;
            *reinterpret_cast<uint2*>(sAhi + off) = hp;
            *reinterpret_cast<uint2*>(sAlo + off) = lp;
        }
        __syncthreads();

        // prefetch next t (hidden under MMAs)
        if (t + 1 < Tdim) {
            size_t rb = ((size_t)(b * Tdim + t + 1) * Ndim + n0) * 128;
#pragma unroll
            for (int it = 0; it < 2; ++it) {
                int i = tid + it * 256;
                int r = i >> 5, c4 = (i & 31) << 2;
                pf[it] = *reinterpret_cast<const float4*>(x + rb + (size_t)r * 128 + c4);
            }
        }

        float acc[2][2][4];   // [blk: 0=primary 1=gating][jj][q]
#pragma unroll
        for (int p = 0; p < 2; ++p)
#pragma unroll
            for (int jj = 0; jj < 2; ++jj)
#pragma unroll
                for (int q = 0; q < 4; ++q) acc[p][jj][q] = 0.0f;

#pragma unroll
        for (int kk = 0; kk < 8; ++kk) {
            const uint32_t ko = kk * 32;
            uint32_t ah[4], al[4], bh[2][4], bl[4];
            LDSM4(ah, aHiAd + ko);
            LDSM4(bh[0], bHiAd[0] + ko);
            LDSM4(bh[1], bHiAd[1] + ko);
            LDSM4(al, aLoAd + ko);
            LDSM4(bl, bLoAd + ko);
            // primary: 3-pass split-bf16
#pragma unroll
            for (int jj = 0; jj < 2; ++jj) {
                const int wh = jj * 2;
                float* d = acc[0][jj];
                MMA16816(d, ah, bh[0][wh], bh[0][wh + 1]);
                MMA16816(d, ah, bl[wh],    bl[wh + 1]);
                MMA16816(d, al, bh[0][wh], bh[0][wh + 1]);
            }
            // gating: 1-pass bf16 (EMA+sigmoid damp the truncation error)
#pragma unroll
            for (int jj = 0; jj < 2; ++jj) {
                const int wh = jj * 2;
                MMA16816(acc[1][jj], ah, bh[1][wh], bh[1][wh + 1]);
            }
        }

        // in-register scan + gate + split, stage to smem for coalesced store
#pragma unroll
        for (int jj = 0; jj < 2; ++jj) {
            float gt[4];
#pragma unroll
            for (int q = 0; q < 4; ++q) {
                float gv = acc[1][jj][q] + bg[jj][q & 1];
                s[jj][q] = fmaf(0.9f, s[jj][q], 0.1f * gv);
                float sig = 1.0f / (1.0f + __expf(-s[jj][q]));
                gt[q] = (acc[0][jj][q] + bp[jj][q & 1]) * sig;
            }
            const int col = 16 * wid + jj * 8 + gc;
#pragma unroll
            for (int h2 = 0; h2 < 2; ++h2) {
                float2 pr2 = make_float2(gt[h2 * 2], gt[h2 * 2 + 1]);
                __nv_bfloat162 hi2 = __float22bfloat162_rn(pr2);
                float2 hif = __bfloat1622float2(hi2);
                __nv_bfloat162 lo2 = __float22bfloat162_rn(
                    make_float2(pr2.x - hif.x, pr2.y - hif.y));
                int row = gr + h2 * 8;
                *reinterpret_cast<uint32_t*>(sGhi + row * LDS_STRIDE + col) =
                    *reinterpret_cast<uint32_t*>(&hi2);
                *reinterpret_cast<uint32_t*>(sGlo + row * LDS_STRIDE + col) =
                    *reinterpret_cast<uint32_t*>(&lo2);
            }
        }
        __syncthreads();

        // coalesced store of gated planes: 16 rows x 128 bf16 each
        {
            int r = tid >> 4, c8 = (tid & 15) << 3;
            uint4 vh = *reinterpret_cast<const uint4*>(sGhi + r * LDS_STRIDE + c8);
            uint4 vl = *reinterpret_cast<const uint4*>(sGlo + r * LDS_STRIDE + c8);
            size_t g = ((size_t)(b * Tdim + t) * Ndim + n0 + r) * 128 + c8;
            *reinterpret_cast<uint4*>(g_gHi + g) = vh;
            *reinterpret_cast<uint4*>(g_gLo + g) = vl;
        }
    }
}

// ---------------- GEMM2 (persistent, 128-row tiles): out = gated*W_con^T + b ----------------
__global__ __launch_bounds__(512, 1)
void gemm2_p(const float* __restrict__ W_con, const float* __restrict__ bias,
             float* __restrict__ C) {
    extern __shared__ char smem[];
    __nv_bfloat16* sWhi = reinterpret_cast<__nv_bfloat16*>(smem);   // 128 rows
    __nv_bfloat16* sWlo = sWhi + 128 * LDS_STRIDE;
    __nv_bfloat16* sAhi = sWlo + 128 * LDS_STRIDE;                  // 128 rows
    __nv_bfloat16* sAlo = sAhi + 128 * LDS_STRIDE;

    const int tid  = threadIdx.x;
    const int wid  = tid >> 5;
    const int lane = tid & 31;

    // convert W_con fp32 -> split bf16 smem (one-time)
#pragma unroll
    for (int it = 0; it < 8; ++it) {
        int i = tid + it * 512;        // 4096 float4
        int r = i >> 5;
        int c4 = (i & 31) << 2;
        float4 v = *reinterpret_cast<const float4*>(W_con + (size_t)r * 128 + c4);
        uint2 hp, lp;
        split4(v, hp, lp);
        int off = r * LDS_STRIDE + c4;
        *reinterpret_cast<uint2*>(sWhi + off) = hp;
        *reinterpret_cast<uint2*>(sWlo + off) = lp;
    }

    // warp layout: 4m x 4n, each 32x32 of 128x128 tile
    const int m0 = (wid & 3) * 32;
    const int n0 = (wid >> 2) * 32;

    uint32_t aHiAd[2], aLoAd[2], bHiAd[2], bLoAd[2];
    {
        const uint32_t aBH = smem_u32(sAhi), aBL = smem_u32(sAlo);
        const uint32_t bBH = smem_u32(sWhi), bBL = smem_u32(sWlo);
        int ar = m0 + (lane & 15);
        int ac = (lane >> 4) * 8;
#pragma unroll
        for (int i = 0; i < 2; ++i) {
            uint32_t off = ((ar + 16 * i) * LDS_STRIDE + ac) * 2;
            aHiAd[i] = aBH + off;
            aLoAd[i] = aBL + off;
        }
        int br = n0 + ((lane >> 4) << 3) + (lane & 7);
        int bc = ((lane >> 3) & 1) * 8;
#pragma unroll
        for (int j = 0; j < 2; ++j) {
            uint32_t off = ((br + 16 * j) * LDS_STRIDE + bc) * 2;
            bHiAd[j] = bBH + off;
            bLoAd[j] = bBL + off;
        }
    }

    // prefetch tile0: 128x128 bf16 per plane = 2048 uint4, 4/thread/plane
    uint4 pfh[4], pfl[4];
    {
        int t0 = blockIdx.x;
        if (t0 < NT2) {
            const uint4* sh = reinterpret_cast<const uint4*>(g_gHi + (size_t)t0 * 128 * 128);
            const uint4* sl = reinterpret_cast<const uint4*>(g_gLo + (size_t)t0 * 128 * 128);
#pragma unroll
            for (int it = 0; it < 4; ++it) {
                pfh[it] = sh[tid + it * 512];
                pfl[it] = sl[tid + it * 512];
            }
        }
    }

    const int gr = lane >> 2;
    const int gc = (lane & 3) * 2;
    float bv[4][2];
#pragma unroll
    for (int jj = 0; jj < 4; ++jj) {
        bv[jj][0] = bias[n0 + jj * 8 + gc];
        bv[jj][1] = bias[n0 + jj * 8 + gc + 1];
    }

    for (int tile = blockIdx.x; tile < NT2; tile += GRID_P) {
        __syncthreads();
#pragma unroll
        for (int it = 0; it < 4; ++it) {
            int i = tid + it * 512;
            int r = i >> 4, c = (i & 15) << 3;
            *reinterpret_cast<uint4*>(sAhi + r * LDS_STRIDE + c) = pfh[it];
            *reinterpret_cast<uint4*>(sAlo + r * LDS_STRIDE + c) = pfl[it];
        }
        __syncthreads();

        int next = tile + GRID_P;
        if (next < NT2) {
            const uint4* sh = reinterpret_cast<const uint4*>(g_gHi + (size_t)next * 128 * 128);
            const uint4* sl = reinterpret_cast<const uint4*>(g_gLo + (size_t)next * 128 * 128);
#pragma unroll
            for (int it = 0; it < 4; ++it) {
                pfh[it] = sh[tid + it * 512];
                pfl[it] = sl[tid + it * 512];
            }
        }

        float acc[2][4][4];
#pragma unroll
        for (int i = 0; i < 2; ++i)
#pragma unroll
            for (int j = 0; j < 4; ++j)
#pragma unroll
                for (int q = 0; q < 4; ++q) acc[i][j][q] = 0.0f;

#pragma unroll
        for (int kk = 0; kk < 8; ++kk) {
            const uint32_t ko = kk * 32;
            uint32_t ah[2][4], al[2][4], bh[2][4], bl[2][4];
#pragma unroll
            for (int i = 0; i < 2; ++i) { LDSM4(ah[i], aHiAd[i] + ko); }
#pragma unroll
            for (int j = 0; j < 2; ++j) { LDSM4(bh[j], bHiAd[j] + ko); }
#pragma unroll
            for (int i = 0; i < 2; ++i) { LDSM4(al[i], aLoAd[i] + ko); }
#pragma unroll
            for (int j = 0; j < 2; ++j) { LDSM4(bl[j], bLoAd[j] + ko); }
#pragma unroll
            for (int i = 0; i < 2; ++i) {
#pragma unroll
                for (int jj = 0; jj < 4; ++jj) {
                    const int pr = jj >> 1, wh = (jj & 1) * 2;
                    float* d = acc[i][jj];
                    MMA16816(d, ah[i], bh[pr][wh], bh[pr][wh + 1]);
                    MMA16816(d, ah[i], bl[pr][wh], bl[pr][wh + 1]);
                    MMA16816(d, al[i], bh[pr][wh], bh[pr][wh + 1]);
                }
            }
        }

        const int bm0 = tile * 128;
#pragma unroll
        for (int jj = 0; jj < 4; ++jj) {
            const int col = n0 + jj * 8 + gc;
#pragma unroll
            for (int i = 0; i < 2; ++i) {
                const int row = bm0 + m0 + i * 16 + gr;
                float2 o0, o1;
                o0.x = acc[i][jj][0] + bv[jj][0]; o0.y = acc[i][jj][1] + bv[jj][1];
                o1.x = acc[i][jj][2] + bv[jj][0]; o1.y = acc[i][jj][3] + bv[jj][1];
                *reinterpret_cast<float2*>(&C[(size_t)row * 128 + col])       = o0;
                *reinterpret_cast<float2*>(&C[(size_t)(row + 8) * 128 + col]) = o1;
            }
        }
    }
}

// ---------------- launch ----------------
extern "C" void kernel_launch(void* const* d_in, const int* in_sizes, int n_in,
                              void* d_out, int out_size) {
    const float* x     = (const float*)d_in[0];
    const float* W_exp = (const float*)d_in[1];
    const float* b_exp = (const float*)d_in[2];
    const float* W_con = (const float*)d_in[3];
    const float* b_con = (const float*)d_in[4];
    float* out = (float*)d_out;

    constexpr int SMEMF = (2 * 256 + 4 * 16) * LDS_STRIDE * 2;  // 156,672
    constexpr int SMEM2 = 4 * 128 * LDS_STRIDE * 2;             // 139,264
    cudaFuncSetAttribute(gemm1_fused, cudaFuncAttributeMaxDynamicSharedMemorySize, SMEMF);
    cudaFuncSetAttribute(gemm2_p, cudaFuncAttributeMaxDynamicSharedMemorySize, SMEM2);

    split_weights<<<128, 256>>>(W_exp);

    gemm1_fused<<<Bdim * 32, 256, SMEMF>>>(x, b_exp);

    gemm2_p<<<GRID_P, 512, SMEM2>>>(W_con, b_con, out);
}